// round 2
// baseline (speedup 1.0000x reference)
#include <cuda_runtime.h>

// Problem constants
#define KD     512          // IN_FEATS == OUT_FEATS
#define NROWS  8192         // rows of feat_p / output
#define MROWS  8192         // rows of feat_s
#define BM     32           // row tile of C per block
#define BN     64           // M tile per iteration
#define TSTR   516          // padded smem row stride in floats (516 % 4 == 0, bank-friendly)
#define TSTR4  129          // TSTR / 4 (float4 stride)
#define NBLK   (NROWS / BM) // 256 fused blocks

// Scratch (device globals: no allocation allowed in kernel_launch)
__device__ float g_Hp[NROWS * KD];
__device__ float g_Hs[MROWS * KD];
__device__ float g_partials[NBLK];
__device__ float g_scale[1];

// ---------------------------------------------------------------------------
// proj: H = X @ W     X:[R,512]  W:[512,512]  H:[R,512]
// 64x64 tile, BK=16, 256 threads, 4x4 microtile (strided rows/cols).
// ---------------------------------------------------------------------------
__global__ __launch_bounds__(256) void proj_kernel(const float* __restrict__ P,
                                                   const float* __restrict__ S,
                                                   const float* __restrict__ W)
{
    const float* X = (blockIdx.z == 0) ? P : S;
    float* H       = (blockIdx.z == 0) ? g_Hp : g_Hs;

    __shared__ float sA[16][65];   // [k][row], padded
    __shared__ float sB[16][64];   // [k][col]

    const int t  = threadIdx.x;
    const int r0 = blockIdx.y * 64;
    const int c0 = blockIdx.x * 64;
    const int ty = t >> 4, tx = t & 15;

    const int la_r = t >> 2,  la_k = (t & 3) << 2;   // A loader: 64 rows x 4 float4
    const int lb_k = t >> 4,  lb_c = (t & 15) << 2;  // B loader: 16 rows x 16 float4

    float acc[4][4];
    #pragma unroll
    for (int i = 0; i < 4; i++)
        #pragma unroll
        for (int j = 0; j < 4; j++) acc[i][j] = 0.f;

    for (int k0 = 0; k0 < KD; k0 += 16) {
        float4 va = *(const float4*)(X + (size_t)(r0 + la_r) * KD + k0 + la_k);
        sA[la_k + 0][la_r] = va.x;
        sA[la_k + 1][la_r] = va.y;
        sA[la_k + 2][la_r] = va.z;
        sA[la_k + 3][la_r] = va.w;
        *(float4*)(&sB[lb_k][lb_c]) =
            *(const float4*)(W + (size_t)(k0 + lb_k) * KD + c0 + lb_c);
        __syncthreads();

        #pragma unroll
        for (int kk = 0; kk < 16; kk++) {
            float ra[4], rb[4];
            #pragma unroll
            for (int i = 0; i < 4; i++) ra[i] = sA[kk][ty + 16 * i];
            #pragma unroll
            for (int j = 0; j < 4; j++) rb[j] = sB[kk][tx + 16 * j];
            #pragma unroll
            for (int i = 0; i < 4; i++)
                #pragma unroll
                for (int j = 0; j < 4; j++)
                    acc[i][j] = fmaf(ra[i], rb[j], acc[i][j]);
        }
        __syncthreads();
    }

    #pragma unroll
    for (int i = 0; i < 4; i++)
        #pragma unroll
        for (int j = 0; j < 4; j++)
            H[(size_t)(r0 + ty + 16 * i) * KD + c0 + tx + 16 * j] = acc[i][j];
}

// ---------------------------------------------------------------------------
// fused: for a BM-row block, loop all M in BN tiles:
//   S = relu(Hp_blk @ Hs_tile^T)      (32 x 64, into smem)
//   sumsq += sum(S^2)                  (per-thread, reduced at end)
//   acc[32][512] += S @ feat_s_tile    (registers: 64 regs/thread)
// then write unnormalized C and block-partial sumsq.
// ---------------------------------------------------------------------------
__device__ __forceinline__ void fma4(float& acc, const float4 a, const float4 b)
{
    acc = fmaf(a.x, b.x, acc);
    acc = fmaf(a.y, b.y, acc);
    acc = fmaf(a.z, b.z, acc);
    acc = fmaf(a.w, b.w, acc);
}

#define SMEM_FUSED ((BM * TSTR + BN * TSTR + BM * 65) * 4)

__global__ __launch_bounds__(256, 1) void fused_kernel(const float* __restrict__ Vs,
                                                       float* __restrict__ out)
{
    extern __shared__ float sm[];
    float* sHp = sm;                    // [BM][TSTR]  (Hp block, resident)
    float* sT  = sm + BM * TSTR;        // [BN][TSTR]  (Hs tile, then feat_s tile)
    float* sS  = sT + BN * TSTR;        // [BM][65]    (relu'd scores)

    const int t  = threadIdx.x;
    const int r0 = blockIdx.x * BM;

    // Load Hp block once: 32 rows x 128 float4
    {
        const float4* g = (const float4*)(g_Hp + (size_t)r0 * KD);
        float4* d = (float4*)sHp;
        #pragma unroll
        for (int i = 0; i < 16; i++) {
            int f = t + i * 256;
            d[(f >> 7) * TSTR4 + (f & 127)] = g[f];
        }
    }

    float acc[64];
    #pragma unroll
    for (int i = 0; i < 64; i++) acc[i] = 0.f;
    float s2 = 0.f;

    const int ty = t >> 4, tx = t & 15;   // S-phase: rows {2ty,2ty+1}, cols {tx+16m}
    const int crow = t >> 3, cg = t & 7;  // C-phase: row crow, cols {4cg+32m+q}

    const float4* ap0 = (const float4*)sHp + (2 * ty) * TSTR4;
    const float4* ap1 = ap0 + TSTR4;

    for (int j0 = 0; j0 < MROWS; j0 += BN) {
        __syncthreads();   // sT free (prev C-phase reads done)

        // Load Hs tile: 64 rows x 128 float4
        {
            const float4* g = (const float4*)(g_Hs + (size_t)j0 * KD);
            float4* d = (float4*)sT;
            #pragma unroll
            for (int i = 0; i < 32; i++) {
                int f = t + i * 256;
                d[(f >> 7) * TSTR4 + (f & 127)] = g[f];
            }
        }
        __syncthreads();

        // ----- S = Hp_blk @ Hs_tile^T  (2x4 microtile per thread) -----
        float sa[2][4];
        #pragma unroll
        for (int i = 0; i < 2; i++)
            #pragma unroll
            for (int m = 0; m < 4; m++) sa[i][m] = 0.f;
        {
            const float4* b0 = (const float4*)sT + tx * TSTR4;
            const float4* b1 = b0 + 16 * TSTR4;
            const float4* b2 = b0 + 32 * TSTR4;
            const float4* b3 = b0 + 48 * TSTR4;
            #pragma unroll 4
            for (int kq = 0; kq < 128; kq++) {
                float4 a0 = ap0[kq];
                float4 a1 = ap1[kq];
                float4 b;
                b = b0[kq]; fma4(sa[0][0], a0, b); fma4(sa[1][0], a1, b);
                b = b1[kq]; fma4(sa[0][1], a0, b); fma4(sa[1][1], a1, b);
                b = b2[kq]; fma4(sa[0][2], a0, b); fma4(sa[1][2], a1, b);
                b = b3[kq]; fma4(sa[0][3], a0, b); fma4(sa[1][3], a1, b);
            }
        }
        // relu + sumsq + stage S
        #pragma unroll
        for (int i = 0; i < 2; i++)
            #pragma unroll
            for (int m = 0; m < 4; m++) {
                float v = fmaxf(sa[i][m], 0.f);
                s2 = fmaf(v, v, s2);
                sS[(2 * ty + i) * 65 + tx + 16 * m] = v;
            }
        __syncthreads();

        // Load feat_s tile into the same buffer (512-wide rows, same padded stride)
        {
            const float4* g = (const float4*)(Vs + (size_t)j0 * KD);
            float4* d = (float4*)sT;
            #pragma unroll
            for (int i = 0; i < 32; i++) {
                int f = t + i * 256;
                d[(f >> 7) * TSTR4 + (f & 127)] = g[f];
            }
        }
        __syncthreads();

        // ----- acc += S @ feat_s_tile -----
        {
            const float4* vbase = (const float4*)sT + cg;
            const float*  srow  = sS + crow * 65;
            #pragma unroll 2
            for (int s = 0; s < BN; s++) {
                float w = srow[s];
                const float4* vr = vbase + s * TSTR4;
                #pragma unroll
                for (int m = 0; m < 16; m++) {
                    float4 v = vr[8 * m];
                    acc[4 * m + 0] = fmaf(w, v.x, acc[4 * m + 0]);
                    acc[4 * m + 1] = fmaf(w, v.y, acc[4 * m + 1]);
                    acc[4 * m + 2] = fmaf(w, v.z, acc[4 * m + 2]);
                    acc[4 * m + 3] = fmaf(w, v.w, acc[4 * m + 3]);
                }
            }
        }
    }

    // Write unnormalized C (scaled later): thread owns row crow, cols 4cg+32m+q
    {
        float4* orow = (float4*)(out + (size_t)(r0 + crow) * KD);
        #pragma unroll
        for (int m = 0; m < 16; m++)
            orow[cg + 8 * m] = make_float4(acc[4 * m + 0], acc[4 * m + 1],
                                           acc[4 * m + 2], acc[4 * m + 3]);
    }

    // Deterministic block reduction of sumsq
    __syncthreads();
    sS[t] = s2;
    __syncthreads();
    #pragma unroll
    for (int off = 128; off > 0; off >>= 1) {
        if (t < off) sS[t] += sS[t + off];
        __syncthreads();
    }
    if (t == 0) g_partials[blockIdx.x] = sS[0];
}

// ---------------------------------------------------------------------------
// reduce partials -> 1/fro   (single block, deterministic tree)
// ---------------------------------------------------------------------------
__global__ void reduce_kernel()
{
    __shared__ float sm[NBLK];
    int t = threadIdx.x;
    sm[t] = g_partials[t];
    __syncthreads();
    #pragma unroll
    for (int off = NBLK / 2; off > 0; off >>= 1) {
        if (t < off) sm[t] += sm[t + off];
        __syncthreads();
    }
    if (t == 0) g_scale[0] = 1.0f / sqrtf(sm[0]);
}

// ---------------------------------------------------------------------------
// scale output in place
// ---------------------------------------------------------------------------
__global__ __launch_bounds__(256) void scale_kernel(float* __restrict__ out)
{
    const float s = g_scale[0];
    size_t i = (size_t)blockIdx.x * blockDim.x + threadIdx.x;
    float4* o = (float4*)out;
    float4 v = o[i];
    v.x *= s; v.y *= s; v.z *= s; v.w *= s;
    o[i] = v;
}

// ---------------------------------------------------------------------------
extern "C" void kernel_launch(void* const* d_in, const int* in_sizes, int n_in,
                              void* d_out, int out_size)
{
    (void)in_sizes; (void)n_in; (void)out_size;
    const float* feat_p = (const float*)d_in[0];
    const float* feat_s = (const float*)d_in[1];
    const float* weight = (const float*)d_in[2];
    float* out = (float*)d_out;

    cudaFuncSetAttribute(fused_kernel,
                         cudaFuncAttributeMaxDynamicSharedMemorySize, SMEM_FUSED);

    dim3 pg(KD / 64, NROWS / 64, 2);
    proj_kernel<<<pg, 256>>>(feat_p, feat_s, weight);
    fused_kernel<<<NBLK, 256, SMEM_FUSED>>>(feat_s, out);
    reduce_kernel<<<1, NBLK>>>();
    scale_kernel<<<(NROWS * KD) / (4 * 256), 256>>>(out);
}

// round 6
// speedup vs baseline: 4.1941x; 4.1941x over previous
#include <cuda_runtime.h>
#include <cuda_bf16.h>
#include <cstdint>

typedef __nv_bfloat16 bf16;

#define KD  512
#define NR  8192
#define CHUNK 1024            // j-chunk width
#define NCHUNK (NR / CHUNK)   // 8

#define STAGE_ELEMS 15360
#define SMEMSZ 61440
#define MB (1024 * 1024)

// ---- single scratch buffer, carved by offsets (largest logical array 16 MiB) ----
// phase A (proj inputs):  Fp_hi@0  Fp_lo@8M  Fs_hi@16M  Fs_lo@24M
// phase B (chunks): S_hi@0 (16M)  S_lo@16M        (overlays dead Fp/Fs)
// persistent: Wt_hi@32M Wt_lo@32.5M  Hp_hi@33M Hp_lo@41M Hs_hi@49M Hs_lo@57M
//             Vt_hi@65M Vt_lo@73M     total 81M
#define OFF_FP_HI  (0 * MB)
#define OFF_FP_LO  (8 * MB)
#define OFF_FS_HI  (16 * MB)
#define OFF_FS_LO  (24 * MB)
#define OFF_S_HI   (0 * MB)
#define OFF_S_LO   (16 * MB)
#define OFF_WT_HI  (32 * MB)
#define OFF_WT_LO  (32 * MB + 512 * 1024)
#define OFF_HP_HI  (33 * MB)
#define OFF_HP_LO  (41 * MB)
#define OFF_HS_HI  (49 * MB)
#define OFF_HS_LO  (57 * MB)
#define OFF_VT_HI  (65 * MB)
#define OFF_VT_LO  (73 * MB)
#define BUF_BYTES  (81 * MB)

__device__ __align__(1024) char g_buf[BUF_BYTES];
__device__ float g_part[8192];
__device__ float g_scale[1];

// ---------------- helpers ----------------
__device__ __forceinline__ void split_bf(float v, bf16& hi, bf16& lo)
{
    hi = __float2bfloat16(v);
    lo = __float2bfloat16(v - __bfloat162float(hi));
}
__device__ __forceinline__ uint32_t pack2(bf16 a, bf16 b)
{
    return (uint32_t)__bfloat16_as_ushort(a) | ((uint32_t)__bfloat16_as_ushort(b) << 16);
}
__device__ __forceinline__ uint32_t lds_u32(const bf16* p)
{
    return *reinterpret_cast<const uint32_t*>(p);
}
#define MMA_BF16(d, a0, a1, a2, a3, b0, b1)                                   \
    asm volatile(                                                             \
        "mma.sync.aligned.m16n8k16.row.col.f32.bf16.bf16.f32 "                \
        "{%0,%1,%2,%3},{%4,%5,%6,%7},{%8,%9},{%0,%1,%2,%3};"                  \
        : "+f"(d[0]), "+f"(d[1]), "+f"(d[2]), "+f"(d[3])                      \
        : "r"(a0), "r"(a1), "r"(a2), "r"(a3), "r"(b0), "r"(b1))

#define CPA16(dst, src) \
    asm volatile("cp.async.cg.shared.global [%0], [%1], 16;" :: "r"(dst), "l"(src))

// ---------------- elementwise split of feats ----------------
__global__ __launch_bounds__(256) void convert_feats(const float* __restrict__ fp,
                                                     const float* __restrict__ fs)
{
    size_t i = (size_t)blockIdx.x * 256 + threadIdx.x;
    const float4 v = ((const float4*)(blockIdx.y ? fs : fp))[i];
    bf16* Hh = (bf16*)(g_buf + (blockIdx.y ? OFF_FS_HI : OFF_FP_HI));
    bf16* Hl = (bf16*)(g_buf + (blockIdx.y ? OFF_FS_LO : OFF_FP_LO));
    bf16 h0, l0, h1, l1, h2, l2, h3, l3;
    split_bf(v.x, h0, l0); split_bf(v.y, h1, l1);
    split_bf(v.z, h2, l2); split_bf(v.w, h3, l3);
    ((uint2*)Hh)[i] = make_uint2(pack2(h0, h1), pack2(h2, h3));
    ((uint2*)Hl)[i] = make_uint2(pack2(l0, l1), pack2(l2, l3));
}

// ---------------- transpose W (512x512) -> Wt hi/lo ----------------
__global__ void transpose_w(const float* __restrict__ W)
{
    __shared__ float s[32][33];
    int k = blockIdx.y * 32 + threadIdx.y;
    int n = blockIdx.x * 32 + threadIdx.x;
    s[threadIdx.y][threadIdx.x] = W[k * KD + n];
    __syncthreads();
    int nn = blockIdx.x * 32 + threadIdx.y;
    int kk = blockIdx.y * 32 + threadIdx.x;
    float v = s[threadIdx.x][threadIdx.y];
    bf16 h, l; split_bf(v, h, l);
    ((bf16*)(g_buf + OFF_WT_HI))[nn * KD + kk] = h;
    ((bf16*)(g_buf + OFF_WT_LO))[nn * KD + kk] = l;
}

// ---------------- transpose feat_s (8192x512) -> Vt hi/lo (512x8192) ----------
__global__ void transpose_vs(const float* __restrict__ fs)
{
    __shared__ float s[32][33];
    int k = blockIdx.y * 32 + threadIdx.y;
    int n = blockIdx.x * 32 + threadIdx.x;
    s[threadIdx.y][threadIdx.x] = fs[(size_t)k * KD + n];
    __syncthreads();
    int nn = blockIdx.x * 32 + threadIdx.y;
    int kk = blockIdx.y * 32 + threadIdx.x;
    float v = s[threadIdx.x][threadIdx.y];
    bf16 h, l; split_bf(v, h, l);
    ((bf16*)(g_buf + OFF_VT_HI))[(size_t)nn * NR + kk] = h;
    ((bf16*)(g_buf + OFF_VT_LO))[(size_t)nn * NR + kk] = l;
}

// ---------------- unified GEMM: D[128,64] tile = A[128,K] * B[64,K]^T --------
// bf16x3 (hi*hi + hi*lo + lo*hi), two-pass A fragments, compile-time strides.
// MODE 0: split-write bf16 hi/lo       MODE 1: relu + sumsq + split-write
// MODE 2: write f32 (ACCUM -> +=)
extern __shared__ char s_raw[];

template <int MODE, int LDA, int LDB, int KTILES, int LDO, bool ACCUM>
__global__ __launch_bounds__(256, 1) void gemm_kernel(
    const bf16* __restrict__ Ahi, const bf16* __restrict__ Alo,
    const bf16* __restrict__ Bhi, const bf16* __restrict__ Blo,
    bf16* __restrict__ Ohi, bf16* __restrict__ Olo,
    float* __restrict__ Of, int part_off)
{
    bf16* smbase = (bf16*)s_raw;
    const int tid = threadIdx.x, lane = tid & 31, warp = tid >> 5;
    const int wm = (warp >> 1) * 32;
    const int wn = (warp & 1) * 32;
    const int m0 = blockIdx.y * 128, n0 = blockIdx.x * 64;

    const int ra = tid >> 1, ca = (tid & 1) * 16;
    const int rb = tid >> 2, cb = (tid & 3) * 8;
    const bf16* pAh = Ahi + (size_t)(m0 + ra) * LDA + ca;
    const bf16* pAl = Alo + (size_t)(m0 + ra) * LDA + ca;
    const bf16* pBh = Bhi + (size_t)(n0 + rb) * LDB + cb;
    const bf16* pBl = Blo + (size_t)(n0 + rb) * LDB + cb;
    const uint32_t sbase = (uint32_t)__cvta_generic_to_shared(smbase);
    const uint32_t oAh = sbase + (uint32_t)(ra * 40 + ca) * 2;
    const uint32_t oAl = oAh + 10240;
    const uint32_t oBh = sbase + 20480 + (uint32_t)(rb * 40 + cb) * 2;
    const uint32_t oBl = oBh + 5120;

    auto load_stage = [&](int st, int kt) {
        const uint32_t s = (uint32_t)st * 30720u;
        const int ko = kt * 32;
        CPA16(oAh + s,      pAh + ko);
        CPA16(oAh + s + 16, pAh + ko + 8);
        CPA16(oAl + s,      pAl + ko);
        CPA16(oAl + s + 16, pAl + ko + 8);
        CPA16(oBh + s,      pBh + ko);
        CPA16(oBl + s,      pBl + ko);
    };

    float acc[2][4][4];
    #pragma unroll
    for (int a = 0; a < 2; a++)
        #pragma unroll
        for (int b = 0; b < 4; b++)
            #pragma unroll
            for (int c = 0; c < 4; c++) acc[a][b][c] = 0.f;

    load_stage(0, 0);
    asm volatile("cp.async.commit_group;");

    for (int kt = 0; kt < KTILES; kt++) {
        if (kt + 1 < KTILES) load_stage((kt + 1) & 1, kt + 1);
        asm volatile("cp.async.commit_group;");
        asm volatile("cp.async.wait_group 1;");
        __syncthreads();

        const bf16* sb = smbase + (kt & 1) * STAGE_ELEMS;
        const bf16* sB = sb + 10240;
        #pragma unroll
        for (int s = 0; s < 2; s++) {
            const int acol = s * 16 + (lane & 3) * 2;
            uint32_t afr[2][4];

            // pass 1: A_hi -> hi*hi + hi*lo
            #pragma unroll
            for (int mi = 0; mi < 2; mi++) {
                const bf16* p = sb + (wm + mi * 16 + (lane >> 2)) * 40 + acol;
                afr[mi][0] = lds_u32(p);
                afr[mi][1] = lds_u32(p + 8 * 40);
                afr[mi][2] = lds_u32(p + 8);
                afr[mi][3] = lds_u32(p + 8 * 40 + 8);
            }
            #pragma unroll
            for (int ni = 0; ni < 4; ni++) {
                const bf16* p = sB + (wn + ni * 8 + (lane >> 2)) * 40 + acol;
                uint32_t bh0 = lds_u32(p), bh1 = lds_u32(p + 8);
                uint32_t bl0 = lds_u32(p + 2560), bl1 = lds_u32(p + 2560 + 8);
                #pragma unroll
                for (int mi = 0; mi < 2; mi++) {
                    MMA_BF16(acc[mi][ni], afr[mi][0], afr[mi][1], afr[mi][2], afr[mi][3], bh0, bh1);
                    MMA_BF16(acc[mi][ni], afr[mi][0], afr[mi][1], afr[mi][2], afr[mi][3], bl0, bl1);
                }
            }

            // pass 2: A_lo -> lo*hi (reuse afr regs)
            #pragma unroll
            for (int mi = 0; mi < 2; mi++) {
                const bf16* p = sb + 5120 + (wm + mi * 16 + (lane >> 2)) * 40 + acol;
                afr[mi][0] = lds_u32(p);
                afr[mi][1] = lds_u32(p + 8 * 40);
                afr[mi][2] = lds_u32(p + 8);
                afr[mi][3] = lds_u32(p + 8 * 40 + 8);
            }
            #pragma unroll
            for (int ni = 0; ni < 4; ni++) {
                const bf16* p = sB + (wn + ni * 8 + (lane >> 2)) * 40 + acol;
                uint32_t bh0 = lds_u32(p), bh1 = lds_u32(p + 8);
                #pragma unroll
                for (int mi = 0; mi < 2; mi++)
                    MMA_BF16(acc[mi][ni], afr[mi][0], afr[mi][1], afr[mi][2], afr[mi][3], bh0, bh1);
            }
        }
        __syncthreads();
    }

    // ---------------- epilogue ----------------
    float s2 = 0.f;
    #pragma unroll
    for (int mi = 0; mi < 2; mi++)
        #pragma unroll
        for (int ni = 0; ni < 4; ni++) {
            const int m = m0 + wm + mi * 16 + (lane >> 2);
            const int n = n0 + wn + ni * 8 + (lane & 3) * 2;
            float v0 = acc[mi][ni][0], v1 = acc[mi][ni][1];
            float v2 = acc[mi][ni][2], v3 = acc[mi][ni][3];
            if constexpr (MODE == 1) {
                v0 = fmaxf(v0, 0.f); v1 = fmaxf(v1, 0.f);
                v2 = fmaxf(v2, 0.f); v3 = fmaxf(v3, 0.f);
                s2 = fmaf(v0, v0, s2); s2 = fmaf(v1, v1, s2);
                s2 = fmaf(v2, v2, s2); s2 = fmaf(v3, v3, s2);
            }
            if constexpr (MODE == 2) {
                float2* p0 = (float2*)&Of[(size_t)m * LDO + n];
                float2* p1 = (float2*)&Of[(size_t)(m + 8) * LDO + n];
                if constexpr (ACCUM) {
                    float2 o0 = *p0, o1 = *p1;
                    *p0 = make_float2(o0.x + v0, o0.y + v1);
                    *p1 = make_float2(o1.x + v2, o1.y + v3);
                } else {
                    *p0 = make_float2(v0, v1);
                    *p1 = make_float2(v2, v3);
                }
            } else {
                bf16 h0, l0, h1, l1;
                split_bf(v0, h0, l0); split_bf(v1, h1, l1);
                *(uint32_t*)&Ohi[(size_t)m * LDO + n] = pack2(h0, h1);
                *(uint32_t*)&Olo[(size_t)m * LDO + n] = pack2(l0, l1);
                split_bf(v2, h0, l0); split_bf(v3, h1, l1);
                *(uint32_t*)&Ohi[(size_t)(m + 8) * LDO + n] = pack2(h0, h1);
                *(uint32_t*)&Olo[(size_t)(m + 8) * LDO + n] = pack2(l0, l1);
            }
        }

    if constexpr (MODE == 1) {
        __syncthreads();
        float* sf = (float*)s_raw;
        sf[tid] = s2;
        __syncthreads();
        #pragma unroll
        for (int off = 128; off > 0; off >>= 1) {
            if (tid < off) sf[tid] += sf[tid + off];
            __syncthreads();
        }
        if (tid == 0) g_part[part_off + blockIdx.y * gridDim.x + blockIdx.x] = sf[0];
    }
}

// ---------------- reduce 8192 partials -> 1/fro ------------------------------
__global__ void reduce_kernel()
{
    __shared__ float rs[1024];
    int t = threadIdx.x;
    float v = 0.f;
    #pragma unroll
    for (int i = 0; i < 8; i++) v += g_part[t + 1024 * i];
    rs[t] = v;
    __syncthreads();
    #pragma unroll
    for (int off = 512; off > 0; off >>= 1) {
        if (t < off) rs[t] += rs[t + off];
        __syncthreads();
    }
    if (t == 0) g_scale[0] = 1.0f / sqrtf(rs[0]);
}

// ---------------- scale output in place --------------------------------------
__global__ __launch_bounds__(256) void scale_kernel(float* __restrict__ out)
{
    const float s = g_scale[0];
    size_t i = (size_t)blockIdx.x * blockDim.x + threadIdx.x;
    float4* o = (float4*)out;
    float4 v = o[i];
    v.x *= s; v.y *= s; v.z *= s; v.w *= s;
    o[i] = v;
}

// ---------------- launch ----------------
extern "C" void kernel_launch(void* const* d_in, const int* in_sizes, int n_in,
                              void* d_out, int out_size)
{
    (void)in_sizes; (void)n_in; (void)out_size;
    const float* feat_p = (const float*)d_in[0];
    const float* feat_s = (const float*)d_in[1];
    const float* weight = (const float*)d_in[2];
    float* out = (float*)d_out;

    void* basep = nullptr;
    cudaGetSymbolAddress(&basep, g_buf);
    char* base = (char*)basep;
    bf16* Fp_hi = (bf16*)(base + OFF_FP_HI);
    bf16* Fp_lo = (bf16*)(base + OFF_FP_LO);
    bf16* Fs_hi = (bf16*)(base + OFF_FS_HI);
    bf16* Fs_lo = (bf16*)(base + OFF_FS_LO);
    bf16* S_hi  = (bf16*)(base + OFF_S_HI);
    bf16* S_lo  = (bf16*)(base + OFF_S_LO);
    bf16* Wt_hi = (bf16*)(base + OFF_WT_HI);
    bf16* Wt_lo = (bf16*)(base + OFF_WT_LO);
    bf16* Hp_hi = (bf16*)(base + OFF_HP_HI);
    bf16* Hp_lo = (bf16*)(base + OFF_HP_LO);
    bf16* Hs_hi = (bf16*)(base + OFF_HS_HI);
    bf16* Hs_lo = (bf16*)(base + OFF_HS_LO);
    bf16* Vt_hi = (bf16*)(base + OFF_VT_HI);
    bf16* Vt_lo = (bf16*)(base + OFF_VT_LO);

    cudaFuncSetAttribute(gemm_kernel<0, 512, 512, 16, 512, false>,
                         cudaFuncAttributeMaxDynamicSharedMemorySize, SMEMSZ);
    cudaFuncSetAttribute(gemm_kernel<1, 512, 512, 16, CHUNK, false>,
                         cudaFuncAttributeMaxDynamicSharedMemorySize, SMEMSZ);
    cudaFuncSetAttribute(gemm_kernel<2, CHUNK, NR, CHUNK / 32, 512, false>,
                         cudaFuncAttributeMaxDynamicSharedMemorySize, SMEMSZ);
    cudaFuncSetAttribute(gemm_kernel<2, CHUNK, NR, CHUNK / 32, 512, true>,
                         cudaFuncAttributeMaxDynamicSharedMemorySize, SMEMSZ);

    convert_feats<<<dim3(NR * KD / 4 / 256, 2), 256>>>(feat_p, feat_s);
    transpose_w<<<dim3(16, 16), dim3(32, 32)>>>(weight);
    transpose_vs<<<dim3(16, 256), dim3(32, 32)>>>(feat_s);

    // proj: M=8192 N=512 K=512
    gemm_kernel<0, 512, 512, 16, 512, false><<<dim3(8, 64), 256, SMEMSZ>>>(
        Fp_hi, Fp_lo, Wt_hi, Wt_lo, Hp_hi, Hp_lo, nullptr, 0);
    gemm_kernel<0, 512, 512, 16, 512, false><<<dim3(8, 64), 256, SMEMSZ>>>(
        Fs_hi, Fs_lo, Wt_hi, Wt_lo, Hs_hi, Hs_lo, nullptr, 0);

    // chunked S + C accumulation (S_chunk overlays dead Fp/Fs region)
    for (int c = 0; c < NCHUNK; c++) {
        const int j0 = c * CHUNK;
        // S_chunk = relu(Hp @ Hs[j0:j0+CHUNK]^T): M=8192 N=CHUNK K=512
        gemm_kernel<1, 512, 512, 16, CHUNK, false><<<dim3(CHUNK / 64, 64), 256, SMEMSZ>>>(
            Hp_hi, Hp_lo, Hs_hi + (size_t)j0 * 512, Hs_lo + (size_t)j0 * 512,
            S_hi, S_lo, nullptr, c * (CHUNK / 64) * 64);
        // out (+)= S_chunk @ feat_s[j0:j0+CHUNK]: M=8192 N=512 K=CHUNK
        if (c == 0)
            gemm_kernel<2, CHUNK, NR, CHUNK / 32, 512, false><<<dim3(8, 64), 256, SMEMSZ>>>(
                S_hi, S_lo, Vt_hi + j0, Vt_lo + j0, nullptr, nullptr, out, 0);
        else
            gemm_kernel<2, CHUNK, NR, CHUNK / 32, 512, true><<<dim3(8, 64), 256, SMEMSZ>>>(
                S_hi, S_lo, Vt_hi + j0, Vt_lo + j0, nullptr, nullptr, out, 0);
    }

    reduce_kernel<<<1, 1024>>>();
    scale_kernel<<<(NR * KD) / (4 * 256), 256>>>(out);
}